// round 4
// baseline (speedup 1.0000x reference)
#include <cuda_runtime.h>
#include <cuda_bf16.h>
#include <cuda_fp16.h>

#define HIDDEN 16
#define SPLITS 4
#define MAX_V  65536
#define MAX_B  1024

// Scratch (device globals — no allocation allowed)
__device__ __half g_gu_h[MAX_V * HIDDEN];              // fp16 per-vocab g*tanh(u)
__device__ float  g_partial[SPLITS * MAX_B * HIDDEN];  // partial memory sums (fp32)

// ---------------------------------------------------------------------------
// helpers
// ---------------------------------------------------------------------------
__device__ __forceinline__ unsigned long long pack2(float a, float b) {
    unsigned long long r;
    asm("mov.b64 %0, {%1, %2};" : "=l"(r)
        : "r"(__float_as_uint(a)), "r"(__float_as_uint(b)));
    return r;
}
__device__ __forceinline__ void unpack2(unsigned long long p, float& a, float& b) {
    unsigned int lo, hi;
    asm("mov.b64 {%0, %1}, %2;" : "=r"(lo), "=r"(hi) : "l"(p));
    a = __uint_as_float(lo); b = __uint_as_float(hi);
}
__device__ __forceinline__ unsigned long long fma2(unsigned long long a,
                                                   unsigned long long b,
                                                   unsigned long long c) {
    unsigned long long d;
    asm("fma.rn.f32x2 %0, %1, %2, %3;" : "=l"(d) : "l"(a), "l"(b), "l"(c));
    return d;
}

// FFMA-only tanh (odd Taylor through x^17). |x| <= ~0.7 here; abs err < 5e-6.
__device__ __forceinline__ float tanh_poly(float x) {
    float s = x * x;
    float p =              5.9002744e-04f;
    p = fmaf(p, s, -1.4558300e-03f);
    p = fmaf(p, s,  3.5921280e-03f);
    p = fmaf(p, s, -8.8632355e-03f);
    p = fmaf(p, s,  2.1869488e-02f);
    p = fmaf(p, s, -5.3968254e-02f);
    p = fmaf(p, s,  1.3333333e-01f);
    p = fmaf(p, s, -3.3333333e-01f);
    return fmaf(p * s, x, x);
}

// ---------------------------------------------------------------------------
// Kernel A: one thread per OUTPUT ELEMENT (v,k).  804K threads instead of 50K
// -> occupancy ~75% instead of 15%, per-thread critical path cut 16x.
// gu[v][k] = sigmoid(e_v.Wg+bg) * tanh((e_v.Wu)[:,k]+bu[k]), stored fp16.
// ---------------------------------------------------------------------------
__global__ void __launch_bounds__(256)
precompute_gu(const float* __restrict__ embed,
              const float* __restrict__ Wg,
              const float* __restrict__ bg,
              const float* __restrict__ Wu,
              const float* __restrict__ bu,
              int V)
{
    __shared__ float WuS[HIDDEN * HIDDEN];
    __shared__ float WgS[HIDDEN];
    __shared__ float buS[HIDDEN];
    __shared__ float bgS;

    int tid = threadIdx.x;
    if (tid < HIDDEN * HIDDEN) WuS[tid] = Wu[tid];
    if (tid < HIDDEN) { WgS[tid] = Wg[tid]; buS[tid] = bu[tid]; }
    if (tid == 0) bgS = bg[0];
    __syncthreads();

    int gidx = blockIdx.x * 256 + tid;
    int v = gidx >> 4;          // vocab row (16 threads share it)
    int k = gidx & 15;          // output column
    if (v >= V) return;

    // load the shared embedding row (16-way dedup inside the warp)
    float e[HIDDEN];
    const float4* e4 = reinterpret_cast<const float4*>(embed + (size_t)v * HIDDEN);
    #pragma unroll
    for (int j = 0; j < HIDDEN / 4; j++) {
        float4 t = __ldg(&e4[j]);
        e[4*j+0] = t.x; e[4*j+1] = t.y; e[4*j+2] = t.z; e[4*j+3] = t.w;
    }

    // gate (computed redundantly by the 16 threads of a row — 16 FMA, cheap)
    float dg = bgS;
    #pragma unroll
    for (int h = 0; h < HIDDEN; h++) dg = fmaf(e[h], WgS[h], dg);
    float g = fmaf(0.5f, tanh_poly(0.5f * dg), 0.5f);

    // this thread's column dot
    float a = buS[k];
    #pragma unroll
    for (int h = 0; h < HIDDEN; h++) a = fmaf(e[h], WuS[h * HIDDEN + k], a);

    g_gu_h[(size_t)v * HIDDEN + k] = __float2half_rn(g * tanh_poly(a));
}

// ---------------------------------------------------------------------------
// Kernel B: memory_partial[s][b] = sum over a T-chunk of gu[seq[b,t]]
// fp16 table halves the L2 gather traffic (36B/token vs 68B). fp32 accum.
// 64 token-groups x 4 uint2 lanes (each lane = 4 h-components).
// ---------------------------------------------------------------------------
__global__ void accumulate_memory(const int* __restrict__ seq, int B, int T)
{
    int b = blockIdx.x % B;
    int s = blockIdx.x / B;
    int tid = threadIdx.x;
    int c   = tid & 3;       // lane: h range [4c, 4c+4)
    int grp = tid >> 2;      // 0..63 token groups

    int chunk  = (T + SPLITS - 1) / SPLITS;
    int tstart = s * chunk;
    int tend   = min(T, tstart + chunk);

    const int*  srow = seq + (size_t)b * T;
    const uint2* gu2 = reinterpret_cast<const uint2*>(g_gu_h);  // row = 4 uint2

    float4 acc = make_float4(0.f, 0.f, 0.f, 0.f);
    #pragma unroll 8
    for (int t = tstart + grp; t < tend; t += 64) {
        int idx = __ldg(&srow[t]);
        uint2 r = __ldg(&gu2[(size_t)idx * 4 + c]);
        float2 f0 = __half22float2(*reinterpret_cast<__half2*>(&r.x));
        float2 f1 = __half22float2(*reinterpret_cast<__half2*>(&r.y));
        acc.x += f0.x; acc.y += f0.y; acc.z += f1.x; acc.w += f1.y;
    }

    __shared__ float4 red[256];
    red[tid] = acc;
    __syncthreads();
    for (int off = 128; off >= 4; off >>= 1) {
        if (tid < off) {
            float4 a = red[tid], o = red[tid + off];
            a.x += o.x; a.y += o.y; a.z += o.z; a.w += o.w;
            red[tid] = a;
        }
        __syncthreads();
    }
    if (tid < 4) {
        float4* p = reinterpret_cast<float4*>(g_partial);
        p[((size_t)s * B + b) * 4 + tid] = red[tid];   // h = [4*tid, 4*tid+4)
    }
}

// ---------------------------------------------------------------------------
// Kernel C: out[b][v] = sum_h memory[b][h] * Wo[h][v] + bo[v]
// 4 v-lanes/thread, Wo packed in regs once per block, FFMA2 mainloop.
// ---------------------------------------------------------------------------
#define C_VTILE 1024
#define C_BTILE 16
__global__ void __launch_bounds__(256, 2)
output_gemv(const float* __restrict__ Wo,
            const float* __restrict__ bo,
            float* __restrict__ out,
            int B, int V)
{
    __shared__ float memS[C_BTILE * HIDDEN];

    int tid = threadIdx.x;
    int b0  = blockIdx.y * C_BTILE;

    {
        int bl = tid >> 4, h = tid & 15;
        int b = b0 + bl;
        float m = 0.0f;
        if (b < B) {
            #pragma unroll
            for (int s = 0; s < SPLITS; s++)
                m += g_partial[((size_t)s * B + b) * HIDDEN + h];
        }
        memS[tid] = m;
    }

    int v0 = blockIdx.x * C_VTILE + tid;
    int v1 = v0 + 256, v2 = v0 + 512, v3 = v0 + 768;
    bool ok0 = v0 < V, ok1 = v1 < V, ok2 = v2 < V, ok3 = v3 < V;

    unsigned long long wp01[HIDDEN], wp23[HIDDEN];
    #pragma unroll
    for (int h = 0; h < HIDDEN; h++) {
        const float* row = Wo + (size_t)h * V;
        float w0 = ok0 ? __ldg(row + v0) : 0.0f;
        float w1 = ok1 ? __ldg(row + v1) : 0.0f;
        float w2 = ok2 ? __ldg(row + v2) : 0.0f;
        float w3 = ok3 ? __ldg(row + v3) : 0.0f;
        wp01[h] = pack2(w0, w1);
        wp23[h] = pack2(w2, w3);
    }
    unsigned long long bias01 = pack2(ok0 ? __ldg(bo + v0) : 0.0f,
                                      ok1 ? __ldg(bo + v1) : 0.0f);
    unsigned long long bias23 = pack2(ok2 ? __ldg(bo + v2) : 0.0f,
                                      ok3 ? __ldg(bo + v3) : 0.0f);
    __syncthreads();

    int bmax = min(C_BTILE, B - b0);
    for (int bl = 0; bl < bmax; bl++) {
        const float4* m4 = reinterpret_cast<const float4*>(&memS[bl * HIDDEN]);
        float4 ma = m4[0], mb = m4[1], mc = m4[2], md = m4[3];
        unsigned long long a01 = bias01, a23 = bias23;

        #define C_STEP(mv, h) {                                   \
            unsigned long long mm = pack2((mv), (mv));            \
            a01 = fma2(wp01[h], mm, a01);                         \
            a23 = fma2(wp23[h], mm, a23); }
        C_STEP(ma.x, 0)  C_STEP(ma.y, 1)  C_STEP(ma.z, 2)  C_STEP(ma.w, 3)
        C_STEP(mb.x, 4)  C_STEP(mb.y, 5)  C_STEP(mb.z, 6)  C_STEP(mb.w, 7)
        C_STEP(mc.x, 8)  C_STEP(mc.y, 9)  C_STEP(mc.z, 10) C_STEP(mc.w, 11)
        C_STEP(md.x, 12) C_STEP(md.y, 13) C_STEP(md.z, 14) C_STEP(md.w, 15)
        #undef C_STEP

        float r0, r1, r2, r3;
        unpack2(a01, r0, r1);
        unpack2(a23, r2, r3);
        float* orow = out + (size_t)(b0 + bl) * V;
        if (ok0) orow[v0] = r0;
        if (ok1) orow[v1] = r1;
        if (ok2) orow[v2] = r2;
        if (ok3) orow[v3] = r3;
    }
}

// ---------------------------------------------------------------------------
extern "C" void kernel_launch(void* const* d_in, const int* in_sizes, int n_in,
                              void* d_out, int out_size)
{
    const int*   seq   = (const int*)  d_in[0];
    const float* embed = (const float*)d_in[1];
    const float* Wg    = (const float*)d_in[2];
    const float* bg    = (const float*)d_in[3];
    const float* Wu    = (const float*)d_in[4];
    const float* bu    = (const float*)d_in[5];
    const float* Wo    = (const float*)d_in[6];
    const float* bo    = (const float*)d_in[7];
    float*       out   = (float*)d_out;

    int V = in_sizes[7];
    int B = out_size / V;
    int T = in_sizes[0] / B;

    int a_threads = V * HIDDEN;
    precompute_gu<<<(a_threads + 255) / 256, 256>>>(embed, Wg, bg, Wu, bu, V);

    accumulate_memory<<<SPLITS * B, 256>>>(seq, B, T);

    dim3 gridC((V + C_VTILE - 1) / C_VTILE, (B + C_BTILE - 1) / C_BTILE);
    output_gemv<<<gridC, 256>>>(Wo, bo, out, B, V);
}

// round 5
// speedup vs baseline: 1.0616x; 1.0616x over previous
#include <cuda_runtime.h>
#include <cuda_bf16.h>
#include <cuda_fp16.h>

#define HIDDEN 16
#define SPLITS 4
#define MAX_V  65536
#define MAX_B  1024

// Scratch (device globals — no allocation allowed)
__device__ __half g_gu_h[MAX_V * HIDDEN];              // fp16 per-vocab g*tanh(u)
__device__ float  g_partial[SPLITS * MAX_B * HIDDEN];  // partial memory sums (fp32)

// ---------------------------------------------------------------------------
// helpers
// ---------------------------------------------------------------------------
__device__ __forceinline__ unsigned long long pack2(float a, float b) {
    unsigned long long r;
    asm("mov.b64 %0, {%1, %2};" : "=l"(r)
        : "r"(__float_as_uint(a)), "r"(__float_as_uint(b)));
    return r;
}
__device__ __forceinline__ void unpack2(unsigned long long p, float& a, float& b) {
    unsigned int lo, hi;
    asm("mov.b64 {%0, %1}, %2;" : "=r"(lo), "=r"(hi) : "l"(p));
    a = __uint_as_float(lo); b = __uint_as_float(hi);
}
__device__ __forceinline__ unsigned long long fma2(unsigned long long a,
                                                   unsigned long long b,
                                                   unsigned long long c) {
    unsigned long long d;
    asm("fma.rn.f32x2 %0, %1, %2, %3;" : "=l"(d) : "l"(a), "l"(b), "l"(c));
    return d;
}

// FFMA-only tanh (odd Taylor through x^17). |x| <= ~0.7 here; abs err < 5e-6.
__device__ __forceinline__ float tanh_poly(float x) {
    float s = x * x;
    float p =              5.9002744e-04f;
    p = fmaf(p, s, -1.4558300e-03f);
    p = fmaf(p, s,  3.5921280e-03f);
    p = fmaf(p, s, -8.8632355e-03f);
    p = fmaf(p, s,  2.1869488e-02f);
    p = fmaf(p, s, -5.3968254e-02f);
    p = fmaf(p, s,  1.3333333e-01f);
    p = fmaf(p, s, -3.3333333e-01f);
    return fmaf(p * s, x, x);
}

// ---------------------------------------------------------------------------
// Kernel A: one thread per (v, k-QUAD).  4 threads share a vocab row:
// 4x parallelism of thread-per-v (occ ~60%) with only 4x (not 16x) redundancy
// on the embed load + gate. Per thread: 4 update-dots via float4 Wu columns.
// ---------------------------------------------------------------------------
__global__ void __launch_bounds__(256)
precompute_gu(const float* __restrict__ embed,
              const float* __restrict__ Wg,
              const float* __restrict__ bg,
              const float* __restrict__ Wu,
              const float* __restrict__ bu,
              int V)
{
    __shared__ float4 WuS4[HIDDEN * 4];   // [h][kq] = Wu[h][4kq..4kq+3]
    __shared__ float  WgS[HIDDEN];
    __shared__ float4 buS4[4];
    __shared__ float  bgS;

    int tid = threadIdx.x;
    if (tid < HIDDEN * 4) WuS4[tid] = reinterpret_cast<const float4*>(Wu)[tid];
    if (tid < HIDDEN) WgS[tid] = Wg[tid];
    if (tid < 4) buS4[tid] = reinterpret_cast<const float4*>(bu)[tid];
    if (tid == 0) bgS = bg[0];
    __syncthreads();

    int gidx = blockIdx.x * 256 + tid;
    int v  = gidx >> 2;         // vocab row (4 threads share it)
    int kq = gidx & 3;          // k-quad: columns [4kq, 4kq+4)
    if (v >= V) return;

    // full embedding row (L1-broadcast across the 4 sharing threads)
    float e[HIDDEN];
    const float4* e4 = reinterpret_cast<const float4*>(embed + (size_t)v * HIDDEN);
    #pragma unroll
    for (int j = 0; j < HIDDEN / 4; j++) {
        float4 t = __ldg(&e4[j]);
        e[4*j+0] = t.x; e[4*j+1] = t.y; e[4*j+2] = t.z; e[4*j+3] = t.w;
    }

    // gate (4x redundant — 16 FMA + 1 poly, cheap)
    float dg = bgS;
    #pragma unroll
    for (int h = 0; h < HIDDEN; h++) dg = fmaf(e[h], WgS[h], dg);
    float g = fmaf(0.5f, tanh_poly(0.5f * dg), 0.5f);

    // 4 update-dots (float4 accumulator, Wu columns from shared as LDS.128)
    float4 acc = buS4[kq];
    #pragma unroll
    for (int h = 0; h < HIDDEN; h++) {
        float4 w = WuS4[h * 4 + kq];
        float eh = e[h];
        acc.x = fmaf(eh, w.x, acc.x);
        acc.y = fmaf(eh, w.y, acc.y);
        acc.z = fmaf(eh, w.z, acc.z);
        acc.w = fmaf(eh, w.w, acc.w);
    }

    __half2 r01 = __floats2half2_rn(g * tanh_poly(acc.x), g * tanh_poly(acc.y));
    __half2 r23 = __floats2half2_rn(g * tanh_poly(acc.z), g * tanh_poly(acc.w));

    // 8-byte aligned store of the 4 halves
    uint2 packed;
    packed.x = *reinterpret_cast<unsigned int*>(&r01);
    packed.y = *reinterpret_cast<unsigned int*>(&r23);
    reinterpret_cast<uint2*>(g_gu_h)[(size_t)v * 4 + kq] = packed;
}

// ---------------------------------------------------------------------------
// Kernel B: memory_partial[s][b] = sum over a T-chunk of gu[seq[b,t]]
// fp16 table (32B/row gather). fp32 accumulation.
// ---------------------------------------------------------------------------
__global__ void accumulate_memory(const int* __restrict__ seq, int B, int T)
{
    int b = blockIdx.x % B;
    int s = blockIdx.x / B;
    int tid = threadIdx.x;
    int c   = tid & 3;       // lane: h range [4c, 4c+4)
    int grp = tid >> 2;      // 0..63 token groups

    int chunk  = (T + SPLITS - 1) / SPLITS;
    int tstart = s * chunk;
    int tend   = min(T, tstart + chunk);

    const int*  srow = seq + (size_t)b * T;
    const uint2* gu2 = reinterpret_cast<const uint2*>(g_gu_h);  // row = 4 uint2

    float4 acc = make_float4(0.f, 0.f, 0.f, 0.f);
    #pragma unroll 8
    for (int t = tstart + grp; t < tend; t += 64) {
        int idx = __ldg(&srow[t]);
        uint2 r = __ldg(&gu2[(size_t)idx * 4 + c]);
        float2 f0 = __half22float2(*reinterpret_cast<__half2*>(&r.x));
        float2 f1 = __half22float2(*reinterpret_cast<__half2*>(&r.y));
        acc.x += f0.x; acc.y += f0.y; acc.z += f1.x; acc.w += f1.y;
    }

    __shared__ float4 red[256];
    red[tid] = acc;
    __syncthreads();
    for (int off = 128; off >= 4; off >>= 1) {
        if (tid < off) {
            float4 a = red[tid], o = red[tid + off];
            a.x += o.x; a.y += o.y; a.z += o.z; a.w += o.w;
            red[tid] = a;
        }
        __syncthreads();
    }
    if (tid < 4) {
        float4* p = reinterpret_cast<float4*>(g_partial);
        p[((size_t)s * B + b) * 4 + tid] = red[tid];   // h = [4*tid, 4*tid+4)
    }
}

// ---------------------------------------------------------------------------
// Kernel C: out[b][v] = sum_h memory[b][h] * Wo[h][v] + bo[v]
// 4 v-lanes/thread, Wo packed in regs once per block, FFMA2 mainloop.
// ---------------------------------------------------------------------------
#define C_VTILE 1024
#define C_BTILE 16
__global__ void __launch_bounds__(256, 2)
output_gemv(const float* __restrict__ Wo,
            const float* __restrict__ bo,
            float* __restrict__ out,
            int B, int V)
{
    __shared__ float memS[C_BTILE * HIDDEN];

    int tid = threadIdx.x;
    int b0  = blockIdx.y * C_BTILE;

    {
        int bl = tid >> 4, h = tid & 15;
        int b = b0 + bl;
        float m = 0.0f;
        if (b < B) {
            #pragma unroll
            for (int s = 0; s < SPLITS; s++)
                m += g_partial[((size_t)s * B + b) * HIDDEN + h];
        }
        memS[tid] = m;
    }

    int v0 = blockIdx.x * C_VTILE + tid;
    int v1 = v0 + 256, v2 = v0 + 512, v3 = v0 + 768;
    bool ok0 = v0 < V, ok1 = v1 < V, ok2 = v2 < V, ok3 = v3 < V;

    unsigned long long wp01[HIDDEN], wp23[HIDDEN];
    #pragma unroll
    for (int h = 0; h < HIDDEN; h++) {
        const float* row = Wo + (size_t)h * V;
        float w0 = ok0 ? __ldg(row + v0) : 0.0f;
        float w1 = ok1 ? __ldg(row + v1) : 0.0f;
        float w2 = ok2 ? __ldg(row + v2) : 0.0f;
        float w3 = ok3 ? __ldg(row + v3) : 0.0f;
        wp01[h] = pack2(w0, w1);
        wp23[h] = pack2(w2, w3);
    }
    unsigned long long bias01 = pack2(ok0 ? __ldg(bo + v0) : 0.0f,
                                      ok1 ? __ldg(bo + v1) : 0.0f);
    unsigned long long bias23 = pack2(ok2 ? __ldg(bo + v2) : 0.0f,
                                      ok3 ? __ldg(bo + v3) : 0.0f);
    __syncthreads();

    int bmax = min(C_BTILE, B - b0);
    for (int bl = 0; bl < bmax; bl++) {
        const float4* m4 = reinterpret_cast<const float4*>(&memS[bl * HIDDEN]);
        float4 ma = m4[0], mb = m4[1], mc = m4[2], md = m4[3];
        unsigned long long a01 = bias01, a23 = bias23;

        #define C_STEP(mv, h) {                                   \
            unsigned long long mm = pack2((mv), (mv));            \
            a01 = fma2(wp01[h], mm, a01);                         \
            a23 = fma2(wp23[h], mm, a23); }
        C_STEP(ma.x, 0)  C_STEP(ma.y, 1)  C_STEP(ma.z, 2)  C_STEP(ma.w, 3)
        C_STEP(mb.x, 4)  C_STEP(mb.y, 5)  C_STEP(mb.z, 6)  C_STEP(mb.w, 7)
        C_STEP(mc.x, 8)  C_STEP(mc.y, 9)  C_STEP(mc.z, 10) C_STEP(mc.w, 11)
        C_STEP(md.x, 12) C_STEP(md.y, 13) C_STEP(md.z, 14) C_STEP(md.w, 15)
        #undef C_STEP

        float r0, r1, r2, r3;
        unpack2(a01, r0, r1);
        unpack2(a23, r2, r3);
        float* orow = out + (size_t)(b0 + bl) * V;
        if (ok0) orow[v0] = r0;
        if (ok1) orow[v1] = r1;
        if (ok2) orow[v2] = r2;
        if (ok3) orow[v3] = r3;
    }
}

// ---------------------------------------------------------------------------
extern "C" void kernel_launch(void* const* d_in, const int* in_sizes, int n_in,
                              void* d_out, int out_size)
{
    const int*   seq   = (const int*)  d_in[0];
    const float* embed = (const float*)d_in[1];
    const float* Wg    = (const float*)d_in[2];
    const float* bg    = (const float*)d_in[3];
    const float* Wu    = (const float*)d_in[4];
    const float* bu    = (const float*)d_in[5];
    const float* Wo    = (const float*)d_in[6];
    const float* bo    = (const float*)d_in[7];
    float*       out   = (float*)d_out;

    int V = in_sizes[7];
    int B = out_size / V;
    int T = in_sizes[0] / B;

    int a_threads = V * 4;   // thread per (v, k-quad)
    precompute_gu<<<(a_threads + 255) / 256, 256>>>(embed, Wg, bg, Wu, bu, V);

    accumulate_memory<<<SPLITS * B, 256>>>(seq, B, T);

    dim3 gridC((V + C_VTILE - 1) / C_VTILE, (B + C_BTILE - 1) / C_BTILE);
    output_gemv<<<gridC, 256>>>(Wo, bo, out, B, V);
}